// round 4
// baseline (speedup 1.0000x reference)
#include <cuda_runtime.h>
#include <stdint.h>
#include <float.h>

// Shapes: data [64,1024,256] f32, locs [64,256,2] f32, out [64,1024,2500] f32
#define B_  64
#define T_  1024
#define N_  256
#define G_  50
#define GG  2500
#define TPB 256
#define T_PER_BLOCK 32
#define R_  8              // t-rows per barrier window
#define NCH 8              // independent min chains

__device__ uint8_t g_nearest[B_ * GG];

// ---------------------------------------------------------------------------
// Kernel A: argmin_j sqrt((sx-gx)^2+(sy-gy)^2), bit-exact vs jnp reference.
//
// Prefilter key (fast, approximate):  e_j = c_j - 2*sx*gx - 2*sy*gy
// where c_j ~ sx^2+sy^2 (any rounding; same value both passes).
// |e_j - exact| <= ~3e-3 abs; fp32 sqrt-tie class width in d2 <= ~1.5e-3 abs,
// so thresh = e_min + 0.02 conservatively contains every candidate whose
// __fsqrt_rn(d2) could equal the true minimum sqrt.
// Pass 2 computes, for candidates only, the EXACT reference d2 (explicit rn
// mul/add, no contraction) and its sqrt, keeping lexicographic min (s, j)
// via strict < in ascending j  =>  first-index-wins, identical to jnp.argmin.
// ---------------------------------------------------------------------------
__global__ __launch_bounds__(TPB)
void nearest_kernel(const float* __restrict__ locs) {
    __shared__ float4 ssen[N_];   // {sx, sy, c, unused}
    const int b = blockIdx.y;
    const int tid = threadIdx.x;

    {
        float2 l = reinterpret_cast<const float2*>(locs)[b * N_ + tid];
        float sx = __fadd_rn(__fmul_rn(l.x, 25.0f), 25.0f);   // exact ref transform
        float sy = __fadd_rn(__fmul_rn(l.y, 25.0f), 25.0f);
        ssen[tid] = make_float4(sx, sy, sx * sx + sy * sy, 0.0f);
    }
    __syncthreads();

    const int g = blockIdx.x * blockDim.x + tid;
    if (g >= GG) return;

    const float gx  = (float)(g / G_);
    const float gy  = (float)(g % G_);
    const float gx2 = -2.0f * gx;       // exact (small integers)
    const float gy2 = -2.0f * gy;

    // Pass 1: branchless min of prefilter key e_j
    float m[NCH];
    #pragma unroll
    for (int c = 0; c < NCH; ++c) m[c] = FLT_MAX;

    #pragma unroll 4
    for (int i = 0; i < N_ / NCH; ++i) {
        #pragma unroll
        for (int c = 0; c < NCH; ++c) {
            float4 s = ssen[i * NCH + c];
            float e = __fmaf_rn(s.y, gy2, __fmaf_rn(s.x, gx2, s.z));
            m[c] = fminf(m[c], e);
        }
    }
    float emin = m[0];
    #pragma unroll
    for (int c = 1; c < NCH; ++c) emin = fminf(emin, m[c]);
    const float thresh = emin + 0.02f;

    // Pass 2: exact evaluation for rare candidates (ascending j, first-wins)
    float bs = FLT_MAX;
    int   bi = 0;
    #pragma unroll 8
    for (int j = 0; j < N_; ++j) {
        float4 s = ssen[j];
        float e = __fmaf_rn(s.y, gy2, __fmaf_rn(s.x, gx2, s.z));
        if (e <= thresh) {                         // ~1 per cell
            float dx = __fsub_rn(s.x, gx);
            float dy = __fsub_rn(s.y, gy);
            float d2 = __fadd_rn(__fmul_rn(dx, dx), __fmul_rn(dy, dy));
            float sq = __fsqrt_rn(d2);
            if (sq < bs) { bs = sq; bi = j; }      // strict < => first index wins
        }
    }
    g_nearest[b * GG + g] = (uint8_t)bi;
}

// ---------------------------------------------------------------------------
// Kernel B: out[b,t,g] = data[b,t, nearest[b,g]]
// 8 t-rows per barrier window in two transposed float4 smem caches.
// Indices held packed (3 uint32 regs), bytes extracted in-loop.
// ---------------------------------------------------------------------------
__global__ __launch_bounds__(TPB)
void gather_kernel(const float* __restrict__ data, float* __restrict__ out) {
    __shared__ float4 rowsA[N_];     // t-rows 0..3 of window (sensor-major)
    __shared__ float4 rowsB[N_];     // t-rows 4..7

    const int b   = blockIdx.y;
    const int tid = threadIdx.x;

    // this thread's 12 gather indices, packed in 3 words (coalesced LDG)
    uint32_t iw[3] = {0u, 0u, 0u};
    {
        const uint32_t* src = reinterpret_cast<const uint32_t*>(g_nearest + (size_t)b * GG);
        #pragma unroll
        for (int gi = 0; gi < 3; ++gi) {
            int k = tid + gi * TPB;
            if (k < GG / 4) iw[gi] = __ldg(src + k);
        }
    }

    const int t0 = blockIdx.x * T_PER_BLOCK;
    const float* dbase = data + ((size_t)b * T_ + t0) * (size_t)N_;
    float*       obase = out  + ((size_t)b * T_ + t0) * (size_t)GG;

    #pragma unroll 1
    for (int w = 0; w < T_PER_BLOCK / R_; ++w) {
        __syncthreads();
        {
            const float* d0 = dbase + (size_t)(w * R_) * N_ + tid;
            float4 va, vb;
            va.x = __ldcs(d0 + 0 * N_);
            va.y = __ldcs(d0 + 1 * N_);
            va.z = __ldcs(d0 + 2 * N_);
            va.w = __ldcs(d0 + 3 * N_);
            vb.x = __ldcs(d0 + 4 * N_);
            vb.y = __ldcs(d0 + 5 * N_);
            vb.z = __ldcs(d0 + 6 * N_);
            vb.w = __ldcs(d0 + 7 * N_);
            rowsA[tid] = va;
            rowsB[tid] = vb;
        }
        __syncthreads();

        float* o = obase + (size_t)(w * R_) * GG;
        #pragma unroll
        for (int gi = 0; gi < 3; ++gi) {
            int k = tid + gi * TPB;
            if (k < GG / 4) {
                int i0 = (iw[gi] >>  0) & 0xFF;
                int i1 = (iw[gi] >>  8) & 0xFF;
                int i2 = (iw[gi] >> 16) & 0xFF;
                int i3 = (iw[gi] >> 24);
                float4 a0 = rowsA[i0];
                float4 a1 = rowsA[i1];
                float4 a2 = rowsA[i2];
                float4 a3 = rowsA[i3];
                __stcs(reinterpret_cast<float4*>(o + 0 * GG) + k,
                       make_float4(a0.x, a1.x, a2.x, a3.x));
                __stcs(reinterpret_cast<float4*>(o + 1 * GG) + k,
                       make_float4(a0.y, a1.y, a2.y, a3.y));
                __stcs(reinterpret_cast<float4*>(o + 2 * GG) + k,
                       make_float4(a0.z, a1.z, a2.z, a3.z));
                __stcs(reinterpret_cast<float4*>(o + 3 * GG) + k,
                       make_float4(a0.w, a1.w, a2.w, a3.w));
                float4 b0 = rowsB[i0];
                float4 b1 = rowsB[i1];
                float4 b2 = rowsB[i2];
                float4 b3 = rowsB[i3];
                __stcs(reinterpret_cast<float4*>(o + 4 * GG) + k,
                       make_float4(b0.x, b1.x, b2.x, b3.x));
                __stcs(reinterpret_cast<float4*>(o + 5 * GG) + k,
                       make_float4(b0.y, b1.y, b2.y, b3.y));
                __stcs(reinterpret_cast<float4*>(o + 6 * GG) + k,
                       make_float4(b0.z, b1.z, b2.z, b3.z));
                __stcs(reinterpret_cast<float4*>(o + 7 * GG) + k,
                       make_float4(b0.w, b1.w, b2.w, b3.w));
            }
        }
    }
}

// ---------------------------------------------------------------------------
extern "C" void kernel_launch(void* const* d_in, const int* in_sizes, int n_in,
                              void* d_out, int out_size) {
    const float* data = (const float*)d_in[0];
    const float* locs = (const float*)d_in[1];
    if (n_in >= 2 && in_sizes[0] < in_sizes[1]) {
        data = (const float*)d_in[1];
        locs = (const float*)d_in[0];
    }
    float* out = (float*)d_out;

    dim3 gridA((GG + TPB - 1) / TPB, B_);
    nearest_kernel<<<gridA, TPB>>>(locs);

    dim3 gridB(T_ / T_PER_BLOCK, B_);
    gather_kernel<<<gridB, TPB>>>(data, out);
}

// round 5
// speedup vs baseline: 1.0146x; 1.0146x over previous
#include <cuda_runtime.h>
#include <stdint.h>
#include <float.h>

// Shapes: data [64,1024,256] f32, locs [64,256,2] f32, out [64,1024,2500] f32
#define B_   64
#define T_   1024
#define N_   256
#define G_   50
#define GG   2500
#define TPB  256
#define T_PER_BLOCK 32            // t-rows per gather block
#define R_   4                    // t-rows per barrier window
#define NCH  8                    // min chains in producer pass 1
#define PROD_PER_BATCH 10         // producer blocks per batch (10*256 >= 2500)
#define PROD_BLOCKS (B_ * PROD_PER_BATCH)          // 640
#define GATHER_BLOCKS (B_ * (T_ / T_PER_BLOCK))    // 2048

// Scratch + inter-block sync state (zero-init at module load; kernel restores
// zeros before exit => identical behavior on every graph replay).
__device__ uint8_t  g_nearest[B_ * GG];
__device__ unsigned g_ready[B_];   // producer blocks finished for batch b (0..10)
__device__ unsigned g_done[B_];    // gather blocks finished for batch b (0..32)

// ---------------------------------------------------------------------------
// One fused kernel.
//  bid <  640 : producer — exact argmin_j sqrt((sx-gx)^2+(sy-gy)^2) per cell.
//     Pass 1: branchless min of prefilter key e_j = c_j - 2sx*gx - 2sy*gy
//             (|e - exact| <= ~3e-3 abs; fp32 sqrt-tie class width <= ~1.5e-3,
//              so thresh = e_min + 0.02 conservatively covers all candidates).
//     Pass 2: for rare e<=thresh candidates, EXACT reference d2 (rn mul/add,
//             no contraction) + __fsqrt_rn; strict < in ascending j
//             => first-index-wins, bit-identical to jnp.argmin(sqrt(...)).
//  bid >= 640 : consumer — spins until its batch's 10 producers are done,
//     then out[b,t,g] = data[b,t, nearest[b,g]] with transposed float4 row
//     cache + coalesced STG.128 (memory-bound; spin costs hide in idle issue).
// __launch_bounds__(256,5): >=5 resident blocks/SM => wave 1 covers bids
// 0..739, i.e. ALL producers are resident before any consumer can starve them.
// ---------------------------------------------------------------------------
__global__ __launch_bounds__(TPB, 5)
void fused_kernel(const float* __restrict__ data,
                  const float* __restrict__ locs,
                  float* __restrict__ out) {
    __shared__ float4  sbuf[N_];   // producer: {sx,sy,c,-}; consumer: rows4
    __shared__ uint8_t sidx[GG];   // consumer: per-batch gather indices

    const int bid = blockIdx.x;
    const int tid = threadIdx.x;

    if (bid < PROD_BLOCKS) {
        // ----------------------------- producer ---------------------------
        const int b = bid / PROD_PER_BATCH;
        {
            float2 l = reinterpret_cast<const float2*>(locs)[b * N_ + tid];
            float sx = __fadd_rn(__fmul_rn(l.x, 25.0f), 25.0f);  // exact ref transform
            float sy = __fadd_rn(__fmul_rn(l.y, 25.0f), 25.0f);
            sbuf[tid] = make_float4(sx, sy, sx * sx + sy * sy, 0.0f);
        }
        __syncthreads();

        const int g = (bid % PROD_PER_BATCH) * TPB + tid;
        if (g < GG) {
            const float gx  = (float)(g / G_);
            const float gy  = (float)(g % G_);
            const float gx2 = -2.0f * gx;   // exact (small integers)
            const float gy2 = -2.0f * gy;

            float m[NCH];
            #pragma unroll
            for (int c = 0; c < NCH; ++c) m[c] = FLT_MAX;
            #pragma unroll 4
            for (int i = 0; i < N_ / NCH; ++i) {
                #pragma unroll
                for (int c = 0; c < NCH; ++c) {
                    float4 s = sbuf[i * NCH + c];
                    float e = __fmaf_rn(s.y, gy2, __fmaf_rn(s.x, gx2, s.z));
                    m[c] = fminf(m[c], e);
                }
            }
            float emin = m[0];
            #pragma unroll
            for (int c = 1; c < NCH; ++c) emin = fminf(emin, m[c]);
            const float thresh = emin + 0.02f;

            float bs = FLT_MAX;
            int   bi = 0;
            #pragma unroll 8
            for (int j = 0; j < N_; ++j) {
                float4 s = sbuf[j];
                float e = __fmaf_rn(s.y, gy2, __fmaf_rn(s.x, gx2, s.z));
                if (e <= thresh) {                        // ~1 per cell
                    float dx = __fsub_rn(s.x, gx);
                    float dy = __fsub_rn(s.y, gy);
                    float d2 = __fadd_rn(__fmul_rn(dx, dx), __fmul_rn(dy, dy));
                    float sq = __fsqrt_rn(d2);
                    if (sq < bs) { bs = sq; bi = j; }     // first index wins
                }
            }
            g_nearest[b * GG + g] = (uint8_t)bi;
        }
        __threadfence();              // release g_nearest writes
        __syncthreads();
        if (tid == 0) atomicAdd(&g_ready[b], 1u);
        return;
    }

    // ------------------------------- consumer -----------------------------
    const int gbid = bid - PROD_BLOCKS;
    const int b    = gbid >> 5;                       // 32 gather blocks/batch
    const int t0   = (gbid & 31) * T_PER_BLOCK;

    if (tid == 0) {
        while (atomicAdd(&g_ready[b], 0u) < PROD_PER_BATCH) __nanosleep(128);
    }
    __syncthreads();
    __threadfence();                  // acquire g_nearest writes

    {   // stage this batch's 2500 indices into smem (coalesced word loads)
        const uint32_t* src = reinterpret_cast<const uint32_t*>(g_nearest + (size_t)b * GG);
        uint32_t* dst = reinterpret_cast<uint32_t*>(sidx);
        #pragma unroll
        for (int k = tid; k < GG / 4; k += TPB) dst[k] = src[k];
    }
    __syncthreads();

    int idx[3][4];
    #pragma unroll
    for (int gi = 0; gi < 3; ++gi) {
        int k = tid + gi * TPB;
        if (k < GG / 4) {
            idx[gi][0] = sidx[4 * k + 0];
            idx[gi][1] = sidx[4 * k + 1];
            idx[gi][2] = sidx[4 * k + 2];
            idx[gi][3] = sidx[4 * k + 3];
        }
    }

    const float* dbase = data + ((size_t)b * T_ + t0) * (size_t)N_;
    float*       obase = out  + ((size_t)b * T_ + t0) * (size_t)GG;

    #pragma unroll 1
    for (int w = 0; w < T_PER_BLOCK / R_; ++w) {
        __syncthreads();
        {   // stage R_=4 t-rows transposed: thread tid owns sensor tid
            const float* d0 = dbase + (size_t)(w * R_) * N_ + tid;
            float4 v;
            v.x = __ldcs(d0 + 0 * N_);
            v.y = __ldcs(d0 + 1 * N_);
            v.z = __ldcs(d0 + 2 * N_);
            v.w = __ldcs(d0 + 3 * N_);
            sbuf[tid] = v;
        }
        __syncthreads();

        float* o = obase + (size_t)(w * R_) * GG;
        #pragma unroll
        for (int gi = 0; gi < 3; ++gi) {
            int k = tid + gi * TPB;
            if (k < GG / 4) {
                float4 s0 = sbuf[idx[gi][0]];   // LDS.128: 4 t-values each
                float4 s1 = sbuf[idx[gi][1]];
                float4 s2 = sbuf[idx[gi][2]];
                float4 s3 = sbuf[idx[gi][3]];
                __stcs(reinterpret_cast<float4*>(o + 0 * GG) + k,
                       make_float4(s0.x, s1.x, s2.x, s3.x));
                __stcs(reinterpret_cast<float4*>(o + 1 * GG) + k,
                       make_float4(s0.y, s1.y, s2.y, s3.y));
                __stcs(reinterpret_cast<float4*>(o + 2 * GG) + k,
                       make_float4(s0.z, s1.z, s2.z, s3.z));
                __stcs(reinterpret_cast<float4*>(o + 3 * GG) + k,
                       make_float4(s0.w, s1.w, s2.w, s3.w));
            }
        }
    }

    // -------- replay-safe reset: last consumer of batch b clears flags ----
    __syncthreads();
    if (tid == 0) {
        unsigned o = atomicAdd(&g_done[b], 1u);
        if (o == (unsigned)(T_ / T_PER_BLOCK) - 1u) {   // 32nd block
            g_done[b]  = 0u;
            g_ready[b] = 0u;
        }
    }
}

// ---------------------------------------------------------------------------
extern "C" void kernel_launch(void* const* d_in, const int* in_sizes, int n_in,
                              void* d_out, int out_size) {
    const float* data = (const float*)d_in[0];
    const float* locs = (const float*)d_in[1];
    if (n_in >= 2 && in_sizes[0] < in_sizes[1]) {
        data = (const float*)d_in[1];
        locs = (const float*)d_in[0];
    }
    float* out = (float*)d_out;

    fused_kernel<<<PROD_BLOCKS + GATHER_BLOCKS, TPB>>>(data, locs, out);
}

// round 6
// speedup vs baseline: 1.0308x; 1.0160x over previous
#include <cuda_runtime.h>
#include <stdint.h>
#include <float.h>

// Shapes: data [64,1024,256] f32, locs [64,256,2] f32, out [64,1024,2500] f32
#define B_  64
#define T_  1024
#define N_  256
#define G_  50
#define GG  2500
#define TPB 256
#define T_PER_BLOCK 32
#define R_  8                 // t-rows per barrier window (gather)
#define CPT 2                 // cells per thread (nearest)
#define CELLS_PER_BLOCK (TPB * CPT)   // 512
#define NEAREST_BLOCKS_X ((GG + CELLS_PER_BLOCK - 1) / CELLS_PER_BLOCK)  // 5

__device__ uint8_t g_nearest[B_ * GG];

// ---------------------------------------------------------------------------
// Kernel A: argmin_j sqrt((sx-gx)^2+(sy-gy)^2), bit-exact vs jnp reference.
// 2 cells/thread: each sensor float4 LDS feeds both cells (halves LDS stream,
// 4 independent min chains per iteration for ILP).
// Pass 1: branchless min of prefilter key e_j = c_j - 2sx*gx - 2sy*gy.
//   |e - exact_d2 + |g|^2 shift| <= ~3e-3 abs; fp32 sqrt-tie class width in d2
//   <= ~1.5e-3 abs, so thresh = emin + 0.02 covers all possible winners.
// Pass 2: for rare e<=thresh candidates, EXACT reference d2 (explicit rn
//   mul/add, no FMA contraction) + __fsqrt_rn; strict < in ascending j
//   => first-index-wins, identical to jnp.argmin(sqrt(...)).
// ---------------------------------------------------------------------------
__global__ __launch_bounds__(TPB)
void nearest_kernel(const float* __restrict__ locs) {
    __shared__ float4 ssen[N_];   // {sx, sy, c, 0}
    const int b   = blockIdx.y;
    const int tid = threadIdx.x;

    {
        float2 l = reinterpret_cast<const float2*>(locs)[b * N_ + tid];
        float sx = __fadd_rn(__fmul_rn(l.x, 25.0f), 25.0f);  // exact ref transform
        float sy = __fadd_rn(__fmul_rn(l.y, 25.0f), 25.0f);
        ssen[tid] = make_float4(sx, sy, sx * sx + sy * sy, 0.0f);
    }
    __syncthreads();

    const int g0 = blockIdx.x * CELLS_PER_BLOCK + tid;   // cell 0
    const int g1 = g0 + TPB;                             // cell 1
    const bool v0 = (g0 < GG);
    const bool v1 = (g1 < GG);

    const float gxa = (float)(g0 / G_), gya = (float)(g0 % G_);
    const float gxb = (float)(g1 / G_), gyb = (float)(g1 % G_);
    const float axa = -2.0f * gxa, aya = -2.0f * gya;    // exact small ints
    const float axb = -2.0f * gxb, ayb = -2.0f * gyb;

    // Pass 1: branchless e-min, 2 parity chains per cell
    float ma0 = FLT_MAX, ma1 = FLT_MAX, mb0 = FLT_MAX, mb1 = FLT_MAX;
    #pragma unroll 8
    for (int j = 0; j < N_; j += 2) {
        float4 s0 = ssen[j];
        float4 s1 = ssen[j + 1];
        ma0 = fminf(ma0, __fmaf_rn(s0.y, aya, __fmaf_rn(s0.x, axa, s0.z)));
        mb0 = fminf(mb0, __fmaf_rn(s0.y, ayb, __fmaf_rn(s0.x, axb, s0.z)));
        ma1 = fminf(ma1, __fmaf_rn(s1.y, aya, __fmaf_rn(s1.x, axa, s1.z)));
        mb1 = fminf(mb1, __fmaf_rn(s1.y, ayb, __fmaf_rn(s1.x, axb, s1.z)));
    }
    const float ta = fminf(ma0, ma1) + 0.02f;   // thresh, cell 0
    const float tb = fminf(mb0, mb1) + 0.02f;   // thresh, cell 1

    // Pass 2: exact evaluation for rare candidates (ascending j, first-wins)
    float bsa = FLT_MAX, bsb = FLT_MAX;
    int   bia = 0,       bib = 0;
    #pragma unroll 4
    for (int j = 0; j < N_; ++j) {
        float4 s = ssen[j];
        float ea = __fmaf_rn(s.y, aya, __fmaf_rn(s.x, axa, s.z));
        float eb = __fmaf_rn(s.y, ayb, __fmaf_rn(s.x, axb, s.z));
        if (ea <= ta) {                               // ~1 hit per cell
            float dx = __fsub_rn(s.x, gxa);
            float dy = __fsub_rn(s.y, gya);
            float d2 = __fadd_rn(__fmul_rn(dx, dx), __fmul_rn(dy, dy));
            float sq = __fsqrt_rn(d2);
            if (sq < bsa) { bsa = sq; bia = j; }
        }
        if (eb <= tb) {
            float dx = __fsub_rn(s.x, gxb);
            float dy = __fsub_rn(s.y, gyb);
            float d2 = __fadd_rn(__fmul_rn(dx, dx), __fmul_rn(dy, dy));
            float sq = __fsqrt_rn(d2);
            if (sq < bsb) { bsb = sq; bib = j; }
        }
    }
    if (v0) g_nearest[b * GG + g0] = (uint8_t)bia;
    if (v1) g_nearest[b * GG + g1] = (uint8_t)bib;
}

// ---------------------------------------------------------------------------
// Kernel B (R3's best: 121.2us standalone): out[b,t,g] = data[b,t,nearest[b,g]]
// 8 t-rows per barrier window in two transposed float4 smem caches; 24
// independent STG.128 per thread per window.
// ---------------------------------------------------------------------------
__global__ __launch_bounds__(TPB)
void gather_kernel(const float* __restrict__ data, float* __restrict__ out) {
    __shared__ float4  rowsA[N_];
    __shared__ float4  rowsB[N_];
    __shared__ uint8_t sidx[GG];

    const int b   = blockIdx.y;
    const int tid = threadIdx.x;

    {
        const uint32_t* src = reinterpret_cast<const uint32_t*>(g_nearest + (size_t)b * GG);
        uint32_t* dst = reinterpret_cast<uint32_t*>(sidx);
        #pragma unroll
        for (int k = tid; k < GG / 4; k += TPB) dst[k] = src[k];
    }
    __syncthreads();

    int idx[3][4];
    #pragma unroll
    for (int gi = 0; gi < 3; ++gi) {
        int k = tid + gi * TPB;
        if (k < GG / 4) {
            idx[gi][0] = sidx[4 * k + 0];
            idx[gi][1] = sidx[4 * k + 1];
            idx[gi][2] = sidx[4 * k + 2];
            idx[gi][3] = sidx[4 * k + 3];
        }
    }

    const int t0 = blockIdx.x * T_PER_BLOCK;
    const float* dbase = data + ((size_t)b * T_ + t0) * (size_t)N_;
    float*       obase = out  + ((size_t)b * T_ + t0) * (size_t)GG;

    #pragma unroll 1
    for (int w = 0; w < T_PER_BLOCK / R_; ++w) {
        __syncthreads();
        {
            const float* d0 = dbase + (size_t)(w * R_) * N_ + tid;
            float4 va, vb;
            va.x = __ldcs(d0 + 0 * N_);
            va.y = __ldcs(d0 + 1 * N_);
            va.z = __ldcs(d0 + 2 * N_);
            va.w = __ldcs(d0 + 3 * N_);
            vb.x = __ldcs(d0 + 4 * N_);
            vb.y = __ldcs(d0 + 5 * N_);
            vb.z = __ldcs(d0 + 6 * N_);
            vb.w = __ldcs(d0 + 7 * N_);
            rowsA[tid] = va;
            rowsB[tid] = vb;
        }
        __syncthreads();

        float* o = obase + (size_t)(w * R_) * GG;
        #pragma unroll
        for (int gi = 0; gi < 3; ++gi) {
            int k = tid + gi * TPB;
            if (k < GG / 4) {
                float4 a0 = rowsA[idx[gi][0]];
                float4 a1 = rowsA[idx[gi][1]];
                float4 a2 = rowsA[idx[gi][2]];
                float4 a3 = rowsA[idx[gi][3]];
                __stcs(reinterpret_cast<float4*>(o + 0 * GG) + k,
                       make_float4(a0.x, a1.x, a2.x, a3.x));
                __stcs(reinterpret_cast<float4*>(o + 1 * GG) + k,
                       make_float4(a0.y, a1.y, a2.y, a3.y));
                __stcs(reinterpret_cast<float4*>(o + 2 * GG) + k,
                       make_float4(a0.z, a1.z, a2.z, a3.z));
                __stcs(reinterpret_cast<float4*>(o + 3 * GG) + k,
                       make_float4(a0.w, a1.w, a2.w, a3.w));
                float4 b0 = rowsB[idx[gi][0]];
                float4 b1 = rowsB[idx[gi][1]];
                float4 b2 = rowsB[idx[gi][2]];
                float4 b3 = rowsB[idx[gi][3]];
                __stcs(reinterpret_cast<float4*>(o + 4 * GG) + k,
                       make_float4(b0.x, b1.x, b2.x, b3.x));
                __stcs(reinterpret_cast<float4*>(o + 5 * GG) + k,
                       make_float4(b0.y, b1.y, b2.y, b3.y));
                __stcs(reinterpret_cast<float4*>(o + 6 * GG) + k,
                       make_float4(b0.z, b1.z, b2.z, b3.z));
                __stcs(reinterpret_cast<float4*>(o + 7 * GG) + k,
                       make_float4(b0.w, b1.w, b2.w, b3.w));
            }
        }
    }
}

// ---------------------------------------------------------------------------
extern "C" void kernel_launch(void* const* d_in, const int* in_sizes, int n_in,
                              void* d_out, int out_size) {
    const float* data = (const float*)d_in[0];
    const float* locs = (const float*)d_in[1];
    if (n_in >= 2 && in_sizes[0] < in_sizes[1]) {
        data = (const float*)d_in[1];
        locs = (const float*)d_in[0];
    }
    float* out = (float*)d_out;

    dim3 gridA(NEAREST_BLOCKS_X, B_);     // 5 x 64 blocks, 2 cells/thread
    nearest_kernel<<<gridA, TPB>>>(locs);

    dim3 gridB(T_ / T_PER_BLOCK, B_);     // 32 x 64 blocks
    gather_kernel<<<gridB, TPB>>>(data, out);
}